// round 12
// baseline (speedup 1.0000x reference)
#include <cuda_runtime.h>
#include <cfloat>

#define NN 20000
#define EE 320000
#define INDIM 256
#define HID 64
#define NH 4
#define CC 64
#define HC 256
#define DFF 128
#define MT 32
#define SB 500
#define NSB 40

typedef unsigned long long u64;

__device__ __forceinline__ u64 pk2(float x, float y) {
    u64 r; asm("mov.b64 %0,{%1,%2};" : "=l"(r) : "f"(x), "f"(y)); return r;
}
__device__ __forceinline__ void upk2(u64 v, float& x, float& y) {
    asm("mov.b64 {%0,%1},%2;" : "=f"(x), "=f"(y) : "l"(v));
}
__device__ __forceinline__ void ffma2(u64& d, u64 a, u64 b) {
    asm("fma.rn.f32x2 %0,%1,%2,%0;" : "+l"(d) : "l"(a), "l"(b));
}
__device__ __forceinline__ u64 ld2g(const float* p) {
    u64 r; asm("ld.global.nc.b64 %0,[%1];" : "=l"(r) : "l"(p)); return r;
}

// ------------------- scratch -------------------
__device__ float g_xh[NN * HC];
__device__ float g_as[NN * NH];
__device__ float g_ad[NN * NH];
__device__ int   g_indeg[NN];
__device__ int   g_rowptr[NN + 1];
__device__ int   g_cursor[NN];
__device__ int   g_col[EE + NN];
__device__ float g_agg[NN * HC];
__device__ int   g_bsum[NSB];
__device__ int   g_boff[NSB];

// ------------------- embed: h = (x @ We + be) * 8 -------------------
// MT=32 rows, 256 threads: rg=tid>>5 (8 groups x 4 rows), cg=tid&31 (2 cols).
__global__ __launch_bounds__(256) void embed_kernel(const float* __restrict__ x,
                                                    const float* __restrict__ We,
                                                    const float* __restrict__ be,
                                                    float* __restrict__ h) {
    __shared__ u64 As2[MT][65];
    int tid = threadIdx.x;
    int rg = tid >> 5, cg = tid & 31;
    int row0 = blockIdx.x * MT;
    u64 acc[4];
    #pragma unroll
    for (int r = 0; r < 4; r++) acc[r] = 0ull;

    for (int kc = 0; kc < INDIM; kc += 64) {
        int r = tid >> 3, seg = tid & 7;   // 32 rows x 8 segs of 8 floats
        int gr = row0 + r;
        float4 v1 = *reinterpret_cast<const float4*>(x + gr * INDIM + kc + seg * 8);
        float4 v2 = *reinterpret_cast<const float4*>(x + gr * INDIM + kc + seg * 8 + 4);
        As2[r][seg * 8 + 0] = pk2(v1.x, v1.x);
        As2[r][seg * 8 + 1] = pk2(v1.y, v1.y);
        As2[r][seg * 8 + 2] = pk2(v1.z, v1.z);
        As2[r][seg * 8 + 3] = pk2(v1.w, v1.w);
        As2[r][seg * 8 + 4] = pk2(v2.x, v2.x);
        As2[r][seg * 8 + 5] = pk2(v2.y, v2.y);
        As2[r][seg * 8 + 6] = pk2(v2.z, v2.z);
        As2[r][seg * 8 + 7] = pk2(v2.w, v2.w);
        __syncthreads();
        #pragma unroll 8
        for (int k = 0; k < 64; k++) {
            u64 b2 = ld2g(We + (kc + k) * HID + 2 * cg);
            #pragma unroll
            for (int r2 = 0; r2 < 4; r2++) ffma2(acc[r2], As2[rg * 4 + r2][k], b2);
        }
        __syncthreads();
    }
    float be0 = __ldg(be + 2 * cg), be1 = __ldg(be + 2 * cg + 1);
    #pragma unroll
    for (int r = 0; r < 4; r++) {
        int gr = row0 + rg * 4 + r;
        float a0, a1; upk2(acc[r], a0, a1);
        float2 o; o.x = (a0 + be0) * 8.0f; o.y = (a1 + be1) * 8.0f;
        *reinterpret_cast<float2*>(h + gr * HID + 2 * cg) = o;
    }
}

// ------------------- CSR build -------------------
__global__ void init_indeg_kernel() {
    int i = blockIdx.x * blockDim.x + threadIdx.x;
    if (i < NN) g_indeg[i] = 1;
}
__global__ void hist_kernel(const int* __restrict__ ei) {
    int e = blockIdx.x * blockDim.x + threadIdx.x;
    if (e < EE) atomicAdd(&g_indeg[ei[EE + e]], 1);
}
__global__ void scan1_kernel() {
    __shared__ int sm[512];
    int t = threadIdx.x, b = blockIdx.x;
    int v = (t < SB) ? g_indeg[b * SB + t] : 0;
    sm[t] = v;
    __syncthreads();
    for (int off = 256; off > 0; off >>= 1) {
        if (t < off) sm[t] += sm[t + off];
        __syncthreads();
    }
    if (t == 0) g_bsum[b] = sm[0];
}
__global__ void scan2_kernel() {
    __shared__ int sm[64];
    int t = threadIdx.x;  // 64 threads
    int v = (t < NSB) ? g_bsum[t] : 0;
    sm[t] = v;
    __syncthreads();
    for (int off = 1; off < 64; off <<= 1) {
        int u = (t >= off) ? sm[t - off] : 0;
        __syncthreads();
        sm[t] += u;
        __syncthreads();
    }
    if (t < NSB) g_boff[t] = sm[t] - v;   // exclusive
    if (t == 0) g_rowptr[NN] = EE + NN;
}
__global__ void scan3_kernel() {
    __shared__ int sm[512];
    int t = threadIdx.x, b = blockIdx.x;
    int v = (t < SB) ? g_indeg[b * SB + t] : 0;
    sm[t] = v;
    __syncthreads();
    for (int off = 1; off < 512; off <<= 1) {
        int u = (t >= off) ? sm[t - off] : 0;
        __syncthreads();
        sm[t] += u;
        __syncthreads();
    }
    if (t < SB) {
        int node = b * SB + t;
        int p = g_boff[b] + sm[t] - v;
        g_rowptr[node] = p;
        g_cursor[node] = p;
    }
}
__global__ void scatter_kernel(const int* __restrict__ ei) {
    int idx = blockIdx.x * blockDim.x + threadIdx.x;
    if (idx >= EE + NN) return;
    int s, d;
    if (idx < EE) { s = ei[idx]; d = ei[EE + idx]; }
    else          { s = d = idx - EE; }
    int p = atomicAdd(&g_cursor[d], 1);
    g_col[p] = s;
}

// ------------------- xh = h @ Wc[l] + fused attention scores -------------------
// MT=32, 256 threads: rg=tid>>5 (8 groups x 4 rows), cg=tid&31, 8 cols (2 per head).
__global__ __launch_bounds__(256) void xh_kernel(const float* __restrict__ h,
                                                 const float* __restrict__ Wc,
                                                 const float* __restrict__ asrc,
                                                 const float* __restrict__ adst) {
    __shared__ u64 As2[MT][65];
    int tid = threadIdx.x;
    int rg = tid >> 5, cg = tid & 31;
    int row0 = blockIdx.x * MT;
    u64 acc[4][4];
    #pragma unroll
    for (int r = 0; r < 4; r++)
        #pragma unroll
        for (int j = 0; j < 4; j++) acc[r][j] = 0ull;

    {
        int r = tid >> 3, seg = tid & 7;   // 32 rows x 8 segs of 8 floats
        int gr = row0 + r;
        float4 v1 = *reinterpret_cast<const float4*>(h + gr * HID + seg * 8);
        float4 v2 = *reinterpret_cast<const float4*>(h + gr * HID + seg * 8 + 4);
        As2[r][seg * 8 + 0] = pk2(v1.x, v1.x);
        As2[r][seg * 8 + 1] = pk2(v1.y, v1.y);
        As2[r][seg * 8 + 2] = pk2(v1.z, v1.z);
        As2[r][seg * 8 + 3] = pk2(v1.w, v1.w);
        As2[r][seg * 8 + 4] = pk2(v2.x, v2.x);
        As2[r][seg * 8 + 5] = pk2(v2.y, v2.y);
        As2[r][seg * 8 + 6] = pk2(v2.z, v2.z);
        As2[r][seg * 8 + 7] = pk2(v2.w, v2.w);
    }
    __syncthreads();
    #pragma unroll 4
    for (int k = 0; k < HID; k++) {
        u64 b[4];
        #pragma unroll
        for (int j = 0; j < 4; j++) b[j] = ld2g(Wc + k * HC + 2 * cg + 64 * j);
        #pragma unroll
        for (int r = 0; r < 4; r++) {
            u64 a2 = As2[rg * 4 + r][k];
            #pragma unroll
            for (int j = 0; j < 4; j++) ffma2(acc[r][j], a2, b[j]);
        }
    }

    float s0[4], s1[4], d0[4], d1[4];
    #pragma unroll
    for (int j = 0; j < 4; j++) {
        upk2(ld2g(asrc + 64 * j + 2 * cg), s0[j], s1[j]);
        upk2(ld2g(adst + 64 * j + 2 * cg), d0[j], d1[j]);
    }

    #pragma unroll
    for (int r = 0; r < 4; r++) {
        int gr = row0 + rg * 4 + r;
        float vs[4], vd[4];
        #pragma unroll
        for (int j = 0; j < 4; j++) {
            float a0, a1; upk2(acc[r][j], a0, a1);
            float2 o; o.x = a0; o.y = a1;
            *reinterpret_cast<float2*>(g_xh + gr * HC + 2 * cg + 64 * j) = o;
            vs[j] = a0 * s0[j] + a1 * s1[j];
            vd[j] = a0 * d0[j] + a1 * d1[j];
        }
        #pragma unroll
        for (int off = 16; off > 0; off >>= 1) {
            #pragma unroll
            for (int j = 0; j < 4; j++) {
                vs[j] += __shfl_xor_sync(0xFFFFFFFFu, vs[j], off);
                vd[j] += __shfl_xor_sync(0xFFFFFFFFu, vd[j], off);
            }
        }
        if (cg == 0) {
            float4 oS; oS.x = vs[0]; oS.y = vs[1]; oS.z = vs[2]; oS.w = vs[3];
            float4 oD; oD.x = vd[0]; oD.y = vd[1]; oD.z = vd[2]; oD.w = vd[3];
            *reinterpret_cast<float4*>(g_as + gr * NH) = oS;
            *reinterpret_cast<float4*>(g_ad + gr * NH) = oD;
        }
    }
}

// ------------------- attention: warp per dst node, unrolled two-pass softmax -------------------
__device__ __forceinline__ float leaky(float e) { return (e > 0.0f) ? e : 0.2f * e; }

__global__ void attn_kernel(const float* __restrict__ bc) {
    int i = (blockIdx.x * blockDim.x + threadIdx.x) >> 5;
    int lane = threadIdx.x & 31;
    if (i >= NN) return;
    const float4 adv = *reinterpret_cast<const float4*>(g_ad + i * NH);
    float ad[NH] = {adv.x, adv.y, adv.z, adv.w};
    int beg = g_rowptr[i], end = g_rowptr[i + 1];

    // ---- pass 1: per-head max, 4-edge unroll ----
    float m[NH];
    #pragma unroll
    for (int hh = 0; hh < NH; hh++) m[hh] = -FLT_MAX;
    int j = beg;
    for (; j + 4 <= end; j += 4) {
        int sa = __ldg(&g_col[j]),     sb = __ldg(&g_col[j + 1]);
        int sc = __ldg(&g_col[j + 2]), sd = __ldg(&g_col[j + 3]);
        float4 A = __ldg(reinterpret_cast<const float4*>(g_as + sa * NH));
        float4 B = __ldg(reinterpret_cast<const float4*>(g_as + sb * NH));
        float4 C = __ldg(reinterpret_cast<const float4*>(g_as + sc * NH));
        float4 D = __ldg(reinterpret_cast<const float4*>(g_as + sd * NH));
        m[0] = fmaxf(m[0], fmaxf(fmaxf(leaky(A.x + ad[0]), leaky(B.x + ad[0])),
                                 fmaxf(leaky(C.x + ad[0]), leaky(D.x + ad[0]))));
        m[1] = fmaxf(m[1], fmaxf(fmaxf(leaky(A.y + ad[1]), leaky(B.y + ad[1])),
                                 fmaxf(leaky(C.y + ad[1]), leaky(D.y + ad[1]))));
        m[2] = fmaxf(m[2], fmaxf(fmaxf(leaky(A.z + ad[2]), leaky(B.z + ad[2])),
                                 fmaxf(leaky(C.z + ad[2]), leaky(D.z + ad[2]))));
        m[3] = fmaxf(m[3], fmaxf(fmaxf(leaky(A.w + ad[3]), leaky(B.w + ad[3])),
                                 fmaxf(leaky(C.w + ad[3]), leaky(D.w + ad[3]))));
    }
    for (; j < end; j++) {
        int s = __ldg(&g_col[j]);
        float4 A = __ldg(reinterpret_cast<const float4*>(g_as + s * NH));
        m[0] = fmaxf(m[0], leaky(A.x + ad[0]));
        m[1] = fmaxf(m[1], leaky(A.y + ad[1]));
        m[2] = fmaxf(m[2], leaky(A.z + ad[2]));
        m[3] = fmaxf(m[3], leaky(A.w + ad[3]));
    }

    // ---- pass 2: exp-weighted accumulation, 4-edge unroll (24 loads in flight) ----
    float z[NH];
    float2 acc[NH];
    #pragma unroll
    for (int hh = 0; hh < NH; hh++) { z[hh] = 0.0f; acc[hh].x = 0.0f; acc[hh].y = 0.0f; }
    j = beg;
    for (; j + 4 <= end; j += 4) {
        int se[4];
        #pragma unroll
        for (int e = 0; e < 4; e++) se[e] = __ldg(&g_col[j + e]);
        float4 A[4];
        float2 v[4][4];
        #pragma unroll
        for (int e = 0; e < 4; e++) {
            A[e] = __ldg(reinterpret_cast<const float4*>(g_as + se[e] * NH));
            const float* xr = g_xh + se[e] * HC + 2 * lane;
            v[e][0] = __ldg(reinterpret_cast<const float2*>(xr));
            v[e][1] = __ldg(reinterpret_cast<const float2*>(xr + 64));
            v[e][2] = __ldg(reinterpret_cast<const float2*>(xr + 128));
            v[e][3] = __ldg(reinterpret_cast<const float2*>(xr + 192));
        }
        #pragma unroll
        for (int e = 0; e < 4; e++) {
            float av[NH] = {A[e].x, A[e].y, A[e].z, A[e].w};
            #pragma unroll
            for (int hh = 0; hh < NH; hh++) {
                float p = __expf(leaky(av[hh] + ad[hh]) - m[hh]);
                z[hh] += p;
                acc[hh].x = fmaf(p, v[e][hh].x, acc[hh].x);
                acc[hh].y = fmaf(p, v[e][hh].y, acc[hh].y);
            }
        }
    }
    for (; j < end; j++) {
        int s = __ldg(&g_col[j]);
        float4 A = __ldg(reinterpret_cast<const float4*>(g_as + s * NH));
        const float* xr = g_xh + s * HC + 2 * lane;
        float av[NH] = {A.x, A.y, A.z, A.w};
        #pragma unroll
        for (int hh = 0; hh < NH; hh++) {
            float p = __expf(leaky(av[hh] + ad[hh]) - m[hh]);
            z[hh] += p;
            float2 xv = __ldg(reinterpret_cast<const float2*>(xr + hh * CC));
            acc[hh].x = fmaf(p, xv.x, acc[hh].x);
            acc[hh].y = fmaf(p, xv.y, acc[hh].y);
        }
    }
    #pragma unroll
    for (int hh = 0; hh < NH; hh++) {
        float inv = 1.0f / (z[hh] + 1e-16f);
        int c0 = hh * CC + 2 * lane;
        float2 o;
        o.x = acc[hh].x * inv + __ldg(bc + c0);
        o.y = acc[hh].y * inv + __ldg(bc + c0 + 1);
        *reinterpret_cast<float2*>(g_agg + i * HC + c0) = o;
    }
}

// ------------------- FFN + LayerNorm + residual (fused, MT=32, 256 threads) -------------------
__device__ __forceinline__ float gelu_exact(float v) {
    return 0.5f * v * (1.0f + erff(v * 0.7071067811865476f));
}

__global__ __launch_bounds__(256) void ffn_kernel(const float* __restrict__ W1,
                                                  const float* __restrict__ b1,
                                                  const float* __restrict__ W2,
                                                  const float* __restrict__ b2,
                                                  const float* __restrict__ lg,
                                                  const float* __restrict__ lb,
                                                  float* __restrict__ h) {
    __shared__ u64 As2[MT][17];
    __shared__ float Us[MT][DFF];
    int tid = threadIdx.x;
    int rg = tid >> 5, cg = tid & 31;   // rg 0..7 (4 rows each), cg 0..31
    int row0 = blockIdx.x * MT;

    u64 acc[4][2];
    #pragma unroll
    for (int r = 0; r < 4; r++) { acc[r][0] = 0ull; acc[r][1] = 0ull; }

    for (int kc = 0; kc < HC; kc += 16) {
        int r = tid >> 3, seg = tid & 7;   // 32 rows x 8 segs of 2 floats
        int gr = row0 + r;
        float2 v = *reinterpret_cast<const float2*>(g_agg + gr * HC + kc + seg * 2);
        As2[r][seg * 2 + 0] = pk2(v.x, v.x);
        As2[r][seg * 2 + 1] = pk2(v.y, v.y);
        __syncthreads();
        #pragma unroll
        for (int k = 0; k < 16; k++) {
            u64 b0 = ld2g(W1 + (kc + k) * DFF + 2 * cg);
            u64 bb1 = ld2g(W1 + (kc + k) * DFF + 2 * cg + 64);
            #pragma unroll
            for (int r2 = 0; r2 < 4; r2++) {
                u64 a2 = As2[rg * 4 + r2][k];
                ffma2(acc[r2][0], a2, b0);
                ffma2(acc[r2][1], a2, bb1);
            }
        }
        __syncthreads();
    }
    {
        float bi00 = __ldg(b1 + 2 * cg), bi01 = __ldg(b1 + 2 * cg + 1);
        float bi10 = __ldg(b1 + 2 * cg + 64), bi11 = __ldg(b1 + 2 * cg + 65);
        #pragma unroll
        for (int r = 0; r < 4; r++) {
            float a0, a1; upk2(acc[r][0], a0, a1);
            Us[rg * 4 + r][2 * cg]      = gelu_exact(a0 + bi00);
            Us[rg * 4 + r][2 * cg + 1]  = gelu_exact(a1 + bi01);
            upk2(acc[r][1], a0, a1);
            Us[rg * 4 + r][2 * cg + 64] = gelu_exact(a0 + bi10);
            Us[rg * 4 + r][2 * cg + 65] = gelu_exact(a1 + bi11);
        }
    }
    __syncthreads();

    u64 acc2[4];
    #pragma unroll
    for (int r = 0; r < 4; r++) acc2[r] = 0ull;
    #pragma unroll 4
    for (int k = 0; k < DFF; k++) {
        u64 b2v = ld2g(W2 + k * HID + 2 * cg);
        #pragma unroll
        for (int r = 0; r < 4; r++) {
            float a = Us[rg * 4 + r][k];
            ffma2(acc2[r], pk2(a, a), b2v);
        }
    }
    __syncthreads();

    float* Fs = &Us[0][0];
    {
        float c0 = __ldg(b2 + 2 * cg), c1 = __ldg(b2 + 2 * cg + 1);
        #pragma unroll
        for (int r = 0; r < 4; r++) {
            float a0, a1; upk2(acc2[r], a0, a1);
            Fs[(rg * 4 + r) * 65 + 2 * cg]     = a0 + c0;
            Fs[(rg * 4 + r) * 65 + 2 * cg + 1] = a1 + c1;
        }
    }
    __syncthreads();

    {
        int row = tid >> 3, t8 = tid & 7;   // 32 rows, 8 threads/row
        int gr = row0 + row;
        float s = 0.0f, ss = 0.0f;
        #pragma unroll
        for (int c = 0; c < 8; c++) {
            float f = Fs[row * 65 + t8 * 8 + c];
            s += f; ss += f * f;
        }
        s  += __shfl_xor_sync(0xFFFFFFFFu, s, 1);
        s  += __shfl_xor_sync(0xFFFFFFFFu, s, 2);
        s  += __shfl_xor_sync(0xFFFFFFFFu, s, 4);
        ss += __shfl_xor_sync(0xFFFFFFFFu, ss, 1);
        ss += __shfl_xor_sync(0xFFFFFFFFu, ss, 2);
        ss += __shfl_xor_sync(0xFFFFFFFFu, ss, 4);
        float mean = s * (1.0f / HID);
        float var = fmaxf(ss * (1.0f / HID) - mean * mean, 0.0f);
        float rstd = rsqrtf(var + 1e-5f);
        #pragma unroll
        for (int c = 0; c < 8; c++) {
            int col = t8 * 8 + c;
            float y = (Fs[row * 65 + col] - mean) * rstd * __ldg(lg + col) + __ldg(lb + col);
            h[gr * HID + col] += y;
        }
    }
}

// ------------------- launch -------------------
extern "C" void kernel_launch(void* const* d_in, const int* in_sizes, int n_in,
                              void* d_out, int out_size) {
    const float* x       = (const float*)d_in[0];
    const int*   ei      = (const int*)  d_in[1];
    const float* We      = (const float*)d_in[2];
    const float* be      = (const float*)d_in[3];
    const float* Wc      = (const float*)d_in[4];
    const float* att_src = (const float*)d_in[5];
    const float* att_dst = (const float*)d_in[6];
    const float* bc      = (const float*)d_in[7];
    const float* W1      = (const float*)d_in[8];
    const float* b1      = (const float*)d_in[9];
    const float* W2      = (const float*)d_in[10];
    const float* b2      = (const float*)d_in[11];
    const float* ln_g    = (const float*)d_in[12];
    const float* ln_b    = (const float*)d_in[13];
    float* h = (float*)d_out;

    const int MB = NN / MT;   // 625 exactly

    // Ordered so xh_kernel(l=0) sits at captured launch index 3.
    embed_kernel<<<MB, 256>>>(x, We, be, h);                       // 0
    init_indeg_kernel<<<(NN + 255) / 256, 256>>>();                // 1
    hist_kernel<<<(EE + 255) / 256, 256>>>(ei);                    // 2
    xh_kernel<<<MB, 256>>>(h, Wc, att_src, att_dst);               // 3 <- profiled
    scan1_kernel<<<NSB, 512>>>();                                  // 4
    scan2_kernel<<<1, 64>>>();                                     // 5
    scan3_kernel<<<NSB, 512>>>();                                  // 6
    scatter_kernel<<<(EE + NN + 255) / 256, 256>>>(ei);            // 7

    attn_kernel<<<NN / 8, 256>>>(bc);                              // layer 0 attn
    ffn_kernel<<<MB, 256>>>(W1, b1, W2, b2, ln_g, ln_b, h);        // layer 0 ffn

    for (int l = 1; l < 4; l++) {
        xh_kernel<<<MB, 256>>>(h, Wc + l * HID * HC,
                               att_src + l * HC, att_dst + l * HC);
        attn_kernel<<<NN / 8, 256>>>(bc + l * HC);
        ffn_kernel<<<MB, 256>>>(W1 + l * HC * DFF, b1 + l * DFF,
                                W2 + l * DFF * HID, b2 + l * HID,
                                ln_g + l * HID, ln_b + l * HID, h);
    }
}

// round 13
// speedup vs baseline: 1.1020x; 1.1020x over previous
#include <cuda_runtime.h>
#include <cfloat>

#define NN 20000
#define EE 320000
#define INDIM 256
#define HID 64
#define NH 4
#define CC 64
#define HC 256
#define DFF 128
#define MT 32
#define SB 500
#define NSB 40

typedef unsigned long long u64;

__device__ __forceinline__ u64 pk2(float x, float y) {
    u64 r; asm("mov.b64 %0,{%1,%2};" : "=l"(r) : "f"(x), "f"(y)); return r;
}
__device__ __forceinline__ void upk2(u64 v, float& x, float& y) {
    asm("mov.b64 {%0,%1},%2;" : "=f"(x), "=f"(y) : "l"(v));
}
__device__ __forceinline__ void ffma2(u64& d, u64 a, u64 b) {
    asm("fma.rn.f32x2 %0,%1,%2,%0;" : "+l"(d) : "l"(a), "l"(b));
}
__device__ __forceinline__ u64 ld2g(const float* p) {
    u64 r; asm("ld.global.nc.b64 %0,[%1];" : "=l"(r) : "l"(p)); return r;
}
__device__ __forceinline__ ulonglong2 ld4g(const float* p) {
    ulonglong2 r;
    asm("ld.global.nc.v2.b64 {%0,%1},[%2];" : "=l"(r.x), "=l"(r.y) : "l"(p));
    return r;
}

// ------------------- scratch -------------------
__device__ float g_xh[NN * HC];
__device__ float g_as[NN * NH];
__device__ float g_ad[NN * NH];
__device__ int   g_indeg[NN];
__device__ int   g_rowptr[NN + 1];
__device__ int   g_cursor[NN];
__device__ int   g_col[EE + NN];
__device__ float g_agg[NN * HC];
__device__ int   g_bsum[NSB];
__device__ int   g_boff[NSB];

// ------------------- embed: h = (x @ We + be) * 8 -------------------
// MT=32 rows/block, 128 threads: rg=tid>>5 (4 groups x 8 rows), cg=tid&31 (2 cols).
__global__ __launch_bounds__(128) void embed_kernel(const float* __restrict__ x,
                                                    const float* __restrict__ We,
                                                    const float* __restrict__ be,
                                                    float* __restrict__ h) {
    __shared__ u64 As2[MT][65];
    int tid = threadIdx.x;
    int rg = tid >> 5, cg = tid & 31;
    int row0 = blockIdx.x * MT;
    u64 acc[8];
    #pragma unroll
    for (int r = 0; r < 8; r++) acc[r] = 0ull;

    for (int kc = 0; kc < INDIM; kc += 64) {
        int r = tid >> 2, seg = tid & 3;   // 32 rows x 4 segs
        int gr = row0 + r;
        #pragma unroll
        for (int j0 = 0; j0 < 16; j0 += 4) {
            float4 v = *reinterpret_cast<const float4*>(x + gr * INDIM + kc + seg * 16 + j0);
            As2[r][seg * 16 + j0 + 0] = pk2(v.x, v.x);
            As2[r][seg * 16 + j0 + 1] = pk2(v.y, v.y);
            As2[r][seg * 16 + j0 + 2] = pk2(v.z, v.z);
            As2[r][seg * 16 + j0 + 3] = pk2(v.w, v.w);
        }
        __syncthreads();
        #pragma unroll 8
        for (int k = 0; k < 64; k++) {
            u64 b2 = ld2g(We + (kc + k) * HID + 2 * cg);
            #pragma unroll
            for (int r2 = 0; r2 < 8; r2++) ffma2(acc[r2], As2[rg * 8 + r2][k], b2);
        }
        __syncthreads();
    }
    float be0 = __ldg(be + 2 * cg), be1 = __ldg(be + 2 * cg + 1);
    #pragma unroll
    for (int r = 0; r < 8; r++) {
        int gr = row0 + rg * 8 + r;
        float a0, a1; upk2(acc[r], a0, a1);
        float2 o; o.x = (a0 + be0) * 8.0f; o.y = (a1 + be1) * 8.0f;
        *reinterpret_cast<float2*>(h + gr * HID + 2 * cg) = o;
    }
}

// ------------------- CSR build -------------------
__global__ void init_indeg_kernel() {
    int i = blockIdx.x * blockDim.x + threadIdx.x;
    if (i < NN) g_indeg[i] = 1;
}
__global__ void hist_kernel(const int* __restrict__ ei) {
    int e = blockIdx.x * blockDim.x + threadIdx.x;
    if (e < EE) atomicAdd(&g_indeg[ei[EE + e]], 1);
}
__global__ void scan1_kernel() {
    __shared__ int sm[512];
    int t = threadIdx.x, b = blockIdx.x;
    int v = (t < SB) ? g_indeg[b * SB + t] : 0;
    sm[t] = v;
    __syncthreads();
    for (int off = 256; off > 0; off >>= 1) {
        if (t < off) sm[t] += sm[t + off];
        __syncthreads();
    }
    if (t == 0) g_bsum[b] = sm[0];
}
__global__ void scan2_kernel() {
    __shared__ int sm[64];
    int t = threadIdx.x;  // 64 threads
    int v = (t < NSB) ? g_bsum[t] : 0;
    sm[t] = v;
    __syncthreads();
    for (int off = 1; off < 64; off <<= 1) {
        int u = (t >= off) ? sm[t - off] : 0;
        __syncthreads();
        sm[t] += u;
        __syncthreads();
    }
    if (t < NSB) g_boff[t] = sm[t] - v;   // exclusive
    if (t == 0) g_rowptr[NN] = EE + NN;
}
__global__ void scan3_kernel() {
    __shared__ int sm[512];
    int t = threadIdx.x, b = blockIdx.x;
    int v = (t < SB) ? g_indeg[b * SB + t] : 0;
    sm[t] = v;
    __syncthreads();
    for (int off = 1; off < 512; off <<= 1) {
        int u = (t >= off) ? sm[t - off] : 0;
        __syncthreads();
        sm[t] += u;
        __syncthreads();
    }
    if (t < SB) {
        int node = b * SB + t;
        int p = g_boff[b] + sm[t] - v;
        g_rowptr[node] = p;
        g_cursor[node] = p;
    }
}
__global__ void scatter_kernel(const int* __restrict__ ei) {
    int idx = blockIdx.x * blockDim.x + threadIdx.x;
    if (idx >= EE + NN) return;
    int s, d;
    if (idx < EE) { s = ei[idx]; d = ei[EE + idx]; }
    else          { s = d = idx - EE; }
    int p = atomicAdd(&g_cursor[d], 1);
    g_col[p] = s;
}

// ------------------- xh = h @ Wc[l] + fused attention scores -------------------
// MT=32, 128 threads. Lane cg owns 8 CONTIGUOUS cols [8cg, 8cg+8) = 4 f32x2 pairs.
// 8-lane group g = cg>>3 covers head g's 64 columns.
__global__ __launch_bounds__(128) void xh_kernel(const float* __restrict__ h,
                                                 const float* __restrict__ Wc,
                                                 const float* __restrict__ asrc,
                                                 const float* __restrict__ adst) {
    __shared__ u64 As2[MT][65];
    int tid = threadIdx.x;
    int rg = tid >> 5, cg = tid & 31;
    int row0 = blockIdx.x * MT;
    u64 acc[8][4];
    #pragma unroll
    for (int r = 0; r < 8; r++)
        #pragma unroll
        for (int j = 0; j < 4; j++) acc[r][j] = 0ull;

    {
        int r = tid >> 2, seg = tid & 3;
        int gr = row0 + r;
        #pragma unroll
        for (int j0 = 0; j0 < 16; j0 += 4) {
            float4 v = *reinterpret_cast<const float4*>(h + gr * HID + seg * 16 + j0);
            As2[r][seg * 16 + j0 + 0] = pk2(v.x, v.x);
            As2[r][seg * 16 + j0 + 1] = pk2(v.y, v.y);
            As2[r][seg * 16 + j0 + 2] = pk2(v.z, v.z);
            As2[r][seg * 16 + j0 + 3] = pk2(v.w, v.w);
        }
    }
    __syncthreads();
    #pragma unroll 4
    for (int k = 0; k < HID; k++) {
        ulonglong2 b01 = ld4g(Wc + k * HC + 8 * cg);
        ulonglong2 b23 = ld4g(Wc + k * HC + 8 * cg + 4);
        u64 b[4] = {b01.x, b01.y, b23.x, b23.y};
        #pragma unroll
        for (int r = 0; r < 8; r++) {
            u64 a2 = As2[rg * 8 + r][k];
            #pragma unroll
            for (int j = 0; j < 4; j++) ffma2(acc[r][j], a2, b[j]);
        }
    }

    // attention vectors for this lane's 8 columns
    ulonglong2 sv01 = ld4g(asrc + 8 * cg);
    ulonglong2 sv23 = ld4g(asrc + 8 * cg + 4);
    ulonglong2 dv01 = ld4g(adst + 8 * cg);
    ulonglong2 dv23 = ld4g(adst + 8 * cg + 4);
    u64 sp[4] = {sv01.x, sv01.y, sv23.x, sv23.y};
    u64 dp[4] = {dv01.x, dv01.y, dv23.x, dv23.y};
    int head = cg >> 3;

    #pragma unroll
    for (int r = 0; r < 8; r++) {
        int gr = row0 + rg * 8 + r;
        // store raw f32x2 pairs directly (contiguous columns)
        ulonglong2 o0; o0.x = acc[r][0]; o0.y = acc[r][1];
        ulonglong2 o1; o1.x = acc[r][2]; o1.y = acc[r][3];
        *reinterpret_cast<ulonglong2*>(g_xh + gr * HC + 8 * cg) = o0;
        *reinterpret_cast<ulonglong2*>(g_xh + gr * HC + 8 * cg + 4) = o1;
        // scores via packed fma then horizontal add
        u64 vsp = 0ull, vdp = 0ull;
        #pragma unroll
        for (int j = 0; j < 4; j++) {
            ffma2(vsp, acc[r][j], sp[j]);
            ffma2(vdp, acc[r][j], dp[j]);
        }
        float l0, h0, l1, h1;
        upk2(vsp, l0, h0);
        upk2(vdp, l1, h1);
        float vs = l0 + h0, vd = l1 + h1;
        // reduce within 8-lane group (one head per group)
        vs += __shfl_xor_sync(0xFFFFFFFFu, vs, 1);
        vs += __shfl_xor_sync(0xFFFFFFFFu, vs, 2);
        vs += __shfl_xor_sync(0xFFFFFFFFu, vs, 4);
        vd += __shfl_xor_sync(0xFFFFFFFFu, vd, 1);
        vd += __shfl_xor_sync(0xFFFFFFFFu, vd, 2);
        vd += __shfl_xor_sync(0xFFFFFFFFu, vd, 4);
        if ((cg & 7) == 0) {
            g_as[gr * NH + head] = vs;
            g_ad[gr * NH + head] = vd;
        }
    }
}

// ------------------- attention: warp per dst node, unrolled two-pass softmax -------------------
__device__ __forceinline__ float leaky(float e) { return (e > 0.0f) ? e : 0.2f * e; }

__global__ void attn_kernel(const float* __restrict__ bc) {
    int i = (blockIdx.x * blockDim.x + threadIdx.x) >> 5;
    int lane = threadIdx.x & 31;
    if (i >= NN) return;
    const float4 adv = *reinterpret_cast<const float4*>(g_ad + i * NH);
    float ad[NH] = {adv.x, adv.y, adv.z, adv.w};
    int beg = g_rowptr[i], end = g_rowptr[i + 1];

    // ---- pass 1: per-head max, 4-edge unroll ----
    float m[NH];
    #pragma unroll
    for (int hh = 0; hh < NH; hh++) m[hh] = -FLT_MAX;
    int j = beg;
    for (; j + 4 <= end; j += 4) {
        int sa = __ldg(&g_col[j]),     sb = __ldg(&g_col[j + 1]);
        int sc = __ldg(&g_col[j + 2]), sd = __ldg(&g_col[j + 3]);
        float4 A = __ldg(reinterpret_cast<const float4*>(g_as + sa * NH));
        float4 B = __ldg(reinterpret_cast<const float4*>(g_as + sb * NH));
        float4 C = __ldg(reinterpret_cast<const float4*>(g_as + sc * NH));
        float4 D = __ldg(reinterpret_cast<const float4*>(g_as + sd * NH));
        m[0] = fmaxf(m[0], fmaxf(fmaxf(leaky(A.x + ad[0]), leaky(B.x + ad[0])),
                                 fmaxf(leaky(C.x + ad[0]), leaky(D.x + ad[0]))));
        m[1] = fmaxf(m[1], fmaxf(fmaxf(leaky(A.y + ad[1]), leaky(B.y + ad[1])),
                                 fmaxf(leaky(C.y + ad[1]), leaky(D.y + ad[1]))));
        m[2] = fmaxf(m[2], fmaxf(fmaxf(leaky(A.z + ad[2]), leaky(B.z + ad[2])),
                                 fmaxf(leaky(C.z + ad[2]), leaky(D.z + ad[2]))));
        m[3] = fmaxf(m[3], fmaxf(fmaxf(leaky(A.w + ad[3]), leaky(B.w + ad[3])),
                                 fmaxf(leaky(C.w + ad[3]), leaky(D.w + ad[3]))));
    }
    for (; j < end; j++) {
        int s = __ldg(&g_col[j]);
        float4 A = __ldg(reinterpret_cast<const float4*>(g_as + s * NH));
        m[0] = fmaxf(m[0], leaky(A.x + ad[0]));
        m[1] = fmaxf(m[1], leaky(A.y + ad[1]));
        m[2] = fmaxf(m[2], leaky(A.z + ad[2]));
        m[3] = fmaxf(m[3], leaky(A.w + ad[3]));
    }

    // ---- pass 2: exp-weighted accumulation, 2-edge unroll ----
    float z[NH];
    float2 acc[NH];
    #pragma unroll
    for (int hh = 0; hh < NH; hh++) { z[hh] = 0.0f; acc[hh].x = 0.0f; acc[hh].y = 0.0f; }
    j = beg;
    for (; j + 2 <= end; j += 2) {
        int s0 = __ldg(&g_col[j]), s1 = __ldg(&g_col[j + 1]);
        float4 A0 = __ldg(reinterpret_cast<const float4*>(g_as + s0 * NH));
        float4 A1 = __ldg(reinterpret_cast<const float4*>(g_as + s1 * NH));
        const float* x0 = g_xh + s0 * HC + 2 * lane;
        const float* x1 = g_xh + s1 * HC + 2 * lane;
        float2 v00 = __ldg(reinterpret_cast<const float2*>(x0));
        float2 v01 = __ldg(reinterpret_cast<const float2*>(x0 + 64));
        float2 v02 = __ldg(reinterpret_cast<const float2*>(x0 + 128));
        float2 v03 = __ldg(reinterpret_cast<const float2*>(x0 + 192));
        float2 v10 = __ldg(reinterpret_cast<const float2*>(x1));
        float2 v11 = __ldg(reinterpret_cast<const float2*>(x1 + 64));
        float2 v12 = __ldg(reinterpret_cast<const float2*>(x1 + 128));
        float2 v13 = __ldg(reinterpret_cast<const float2*>(x1 + 192));
        float p00 = __expf(leaky(A0.x + ad[0]) - m[0]);
        float p01 = __expf(leaky(A0.y + ad[1]) - m[1]);
        float p02 = __expf(leaky(A0.z + ad[2]) - m[2]);
        float p03 = __expf(leaky(A0.w + ad[3]) - m[3]);
        float p10 = __expf(leaky(A1.x + ad[0]) - m[0]);
        float p11 = __expf(leaky(A1.y + ad[1]) - m[1]);
        float p12 = __expf(leaky(A1.z + ad[2]) - m[2]);
        float p13 = __expf(leaky(A1.w + ad[3]) - m[3]);
        z[0] += p00 + p10; z[1] += p01 + p11; z[2] += p02 + p12; z[3] += p03 + p13;
        acc[0].x = fmaf(p00, v00.x, fmaf(p10, v10.x, acc[0].x));
        acc[0].y = fmaf(p00, v00.y, fmaf(p10, v10.y, acc[0].y));
        acc[1].x = fmaf(p01, v01.x, fmaf(p11, v11.x, acc[1].x));
        acc[1].y = fmaf(p01, v01.y, fmaf(p11, v11.y, acc[1].y));
        acc[2].x = fmaf(p02, v02.x, fmaf(p12, v12.x, acc[2].x));
        acc[2].y = fmaf(p02, v02.y, fmaf(p12, v12.y, acc[2].y));
        acc[3].x = fmaf(p03, v03.x, fmaf(p13, v13.x, acc[3].x));
        acc[3].y = fmaf(p03, v03.y, fmaf(p13, v13.y, acc[3].y));
    }
    for (; j < end; j++) {
        int s = __ldg(&g_col[j]);
        float4 A = __ldg(reinterpret_cast<const float4*>(g_as + s * NH));
        const float* xr = g_xh + s * HC + 2 * lane;
        float av[NH] = {A.x, A.y, A.z, A.w};
        #pragma unroll
        for (int hh = 0; hh < NH; hh++) {
            float p = __expf(leaky(av[hh] + ad[hh]) - m[hh]);
            z[hh] += p;
            float2 xv = __ldg(reinterpret_cast<const float2*>(xr + hh * CC));
            acc[hh].x = fmaf(p, xv.x, acc[hh].x);
            acc[hh].y = fmaf(p, xv.y, acc[hh].y);
        }
    }
    #pragma unroll
    for (int hh = 0; hh < NH; hh++) {
        float inv = 1.0f / (z[hh] + 1e-16f);
        int c0 = hh * CC + 2 * lane;
        float2 o;
        o.x = acc[hh].x * inv + __ldg(bc + c0);
        o.y = acc[hh].y * inv + __ldg(bc + c0 + 1);
        *reinterpret_cast<float2*>(g_agg + i * HC + c0) = o;
    }
}

// ------------------- FFN + LayerNorm + residual (fused, MT=32, 128 threads) -------------------
__device__ __forceinline__ float gelu_exact(float v) {
    return 0.5f * v * (1.0f + erff(v * 0.7071067811865476f));
}

// Stage 1: lane cg owns W1 cols [4cg, 4cg+4) -> 2 f32x2 pairs, 1 LDG.128 per k.
// K staged in 64-wide chunks (4 chunks, 8 syncs total).
__global__ __launch_bounds__(128) void ffn_kernel(const float* __restrict__ W1,
                                                  const float* __restrict__ b1,
                                                  const float* __restrict__ W2,
                                                  const float* __restrict__ b2,
                                                  const float* __restrict__ lg,
                                                  const float* __restrict__ lb,
                                                  float* __restrict__ h) {
    __shared__ u64 As2[MT][65];
    __shared__ float Us[MT][DFF];
    int tid = threadIdx.x;
    int rg = tid >> 5, cg = tid & 31;
    int row0 = blockIdx.x * MT;

    u64 acc[8][2];
    #pragma unroll
    for (int r = 0; r < 8; r++) { acc[r][0] = 0ull; acc[r][1] = 0ull; }

    for (int kc = 0; kc < HC; kc += 64) {
        int r = tid >> 2, seg = tid & 3;   // 32 rows x 4 segs of 16 floats
        int gr = row0 + r;
        #pragma unroll
        for (int j0 = 0; j0 < 16; j0 += 4) {
            float4 v = *reinterpret_cast<const float4*>(g_agg + gr * HC + kc + seg * 16 + j0);
            As2[r][seg * 16 + j0 + 0] = pk2(v.x, v.x);
            As2[r][seg * 16 + j0 + 1] = pk2(v.y, v.y);
            As2[r][seg * 16 + j0 + 2] = pk2(v.z, v.z);
            As2[r][seg * 16 + j0 + 3] = pk2(v.w, v.w);
        }
        __syncthreads();
        #pragma unroll 8
        for (int k = 0; k < 64; k++) {
            ulonglong2 bv = ld4g(W1 + (kc + k) * DFF + 4 * cg);
            #pragma unroll
            for (int r2 = 0; r2 < 8; r2++) {
                u64 a2 = As2[rg * 8 + r2][k];
                ffma2(acc[r2][0], a2, bv.x);
                ffma2(acc[r2][1], a2, bv.y);
            }
        }
        __syncthreads();
    }
    {
        float4 bi = __ldg(reinterpret_cast<const float4*>(b1 + 4 * cg));
        #pragma unroll
        for (int r = 0; r < 8; r++) {
            float a0, a1, a2, a3;
            upk2(acc[r][0], a0, a1);
            upk2(acc[r][1], a2, a3);
            Us[rg * 8 + r][4 * cg + 0] = gelu_exact(a0 + bi.x);
            Us[rg * 8 + r][4 * cg + 1] = gelu_exact(a1 + bi.y);
            Us[rg * 8 + r][4 * cg + 2] = gelu_exact(a2 + bi.z);
            Us[rg * 8 + r][4 * cg + 3] = gelu_exact(a3 + bi.w);
        }
    }
    __syncthreads();

    // Stage 2: F = U @ W2 + b2  (lane cg owns cols {2cg, 2cg+1})
    u64 acc2[8];
    #pragma unroll
    for (int r = 0; r < 8; r++) acc2[r] = 0ull;
    #pragma unroll 4
    for (int k = 0; k < DFF; k++) {
        u64 b2v = ld2g(W2 + k * HID + 2 * cg);
        #pragma unroll
        for (int r = 0; r < 8; r++) {
            float a = Us[rg * 8 + r][k];
            ffma2(acc2[r], pk2(a, a), b2v);
        }
    }
    __syncthreads();

    float* Fs = &Us[0][0];
    {
        float c0 = __ldg(b2 + 2 * cg), c1 = __ldg(b2 + 2 * cg + 1);
        #pragma unroll
        for (int r = 0; r < 8; r++) {
            float a0, a1; upk2(acc2[r], a0, a1);
            Fs[(rg * 8 + r) * 65 + 2 * cg]     = a0 + c0;
            Fs[(rg * 8 + r) * 65 + 2 * cg + 1] = a1 + c1;
        }
    }
    __syncthreads();

    {
        int row = tid >> 2, t4 = tid & 3;   // 32 rows, 4 threads/row
        int gr = row0 + row;
        float s = 0.0f, ss = 0.0f;
        #pragma unroll
        for (int c = 0; c < 16; c++) {
            float f = Fs[row * 65 + t4 * 16 + c];
            s += f; ss += f * f;
        }
        s  += __shfl_xor_sync(0xFFFFFFFFu, s, 1);
        s  += __shfl_xor_sync(0xFFFFFFFFu, s, 2);
        ss += __shfl_xor_sync(0xFFFFFFFFu, ss, 1);
        ss += __shfl_xor_sync(0xFFFFFFFFu, ss, 2);
        float mean = s * (1.0f / HID);
        float var = fmaxf(ss * (1.0f / HID) - mean * mean, 0.0f);
        float rstd = rsqrtf(var + 1e-5f);
        #pragma unroll
        for (int c = 0; c < 16; c++) {
            int col = t4 * 16 + c;
            float y = (Fs[row * 65 + col] - mean) * rstd * __ldg(lg + col) + __ldg(lb + col);
            h[gr * HID + col] += y;
        }
    }
}

// ------------------- launch -------------------
extern "C" void kernel_launch(void* const* d_in, const int* in_sizes, int n_in,
                              void* d_out, int out_size) {
    const float* x       = (const float*)d_in[0];
    const int*   ei      = (const int*)  d_in[1];
    const float* We      = (const float*)d_in[2];
    const float* be      = (const float*)d_in[3];
    const float* Wc      = (const float*)d_in[4];
    const float* att_src = (const float*)d_in[5];
    const float* att_dst = (const float*)d_in[6];
    const float* bc      = (const float*)d_in[7];
    const float* W1      = (const float*)d_in[8];
    const float* b1      = (const float*)d_in[9];
    const float* W2      = (const float*)d_in[10];
    const float* b2      = (const float*)d_in[11];
    const float* ln_g    = (const float*)d_in[12];
    const float* ln_b    = (const float*)d_in[13];
    float* h = (float*)d_out;

    const int MB = NN / MT;   // 625 exactly

    // Ordered so xh_kernel(l=0) sits at captured launch index 3.
    embed_kernel<<<MB, 128>>>(x, We, be, h);                       // 0
    init_indeg_kernel<<<(NN + 255) / 256, 256>>>();                // 1
    hist_kernel<<<(EE + 255) / 256, 256>>>(ei);                    // 2
    xh_kernel<<<MB, 128>>>(h, Wc, att_src, att_dst);               // 3 <- profiled
    scan1_kernel<<<NSB, 512>>>();                                  // 4
    scan2_kernel<<<1, 64>>>();                                     // 5
    scan3_kernel<<<NSB, 512>>>();                                  // 6
    scatter_kernel<<<(EE + NN + 255) / 256, 256>>>(ei);            // 7

    attn_kernel<<<NN / 8, 256>>>(bc);                              // layer 0 attn
    ffn_kernel<<<MB, 128>>>(W1, b1, W2, b2, ln_g, ln_b, h);        // layer 0 ffn

    for (int l = 1; l < 4; l++) {
        xh_kernel<<<MB, 128>>>(h, Wc + l * HID * HC,
                               att_src + l * HC, att_dst + l * HC);
        attn_kernel<<<NN / 8, 256>>>(bc + l * HC);
        ffn_kernel<<<MB, 128>>>(W1 + l * HC * DFF, b1 + l * DFF,
                                W2 + l * DFF * HID, b2 + l * HID,
                                ln_g + l * HID, ln_b + l * HID, h);
    }
}